// round 1
// baseline (speedup 1.0000x reference)
#include <cuda_runtime.h>
#include <math.h>

#define NROWS   262144      // 32768 samples * 8 meshes
#define NC      256
#define NTAB    50001
#define VD      36
#define RPC     32          // rows per CTA
#define RPW     4           // rows per warp
#define NTHR    256

typedef unsigned long long u64;

// ---- packed f32x2 helpers (Blackwell FFMA2 path) ----
__device__ __forceinline__ u64 bcast2(float x) {
    u64 r; asm("mov.b64 %0, {%1, %1};" : "=l"(r) : "f"(x)); return r;
}
__device__ __forceinline__ void fma2(u64 &d, u64 a, u64 b) {
    asm("fma.rn.f32x2 %0, %1, %2, %0;" : "+l"(d) : "l"(a), "l"(b));
}
__device__ __forceinline__ float2 unpk(u64 v) {
    float x, y; asm("mov.b64 {%0, %1}, %2;" : "=f"(x), "=f"(y) : "l"(v));
    return make_float2(x, y);
}
__device__ __forceinline__ float fcomp(const float4 &v, int i) {
    return (i == 0) ? v.x : (i == 1) ? v.y : (i == 2) ? v.z : v.w;
}

// Accumulate a K-chunk of a dense layer into packed accumulators.
// Warp layout: 4 rows (r0..r0+3), lane owns cols {lane*4..+3} and {128+lane*4..+3}
// acc[r][0..1] -> cols lane*4 + {0,1},{2,3}; acc[r][2..3] -> cols 128+lane*4 + {0,1},{2,3}
template<int K, int AST>
__device__ __forceinline__ void acc_block(u64 acc[RPW][4],
        const float *act, const float* __restrict__ W,
        int ldw, int colBase, int r0, int lane)
{
    const float* wbase = W + colBase + lane * 4;
#pragma unroll 2
    for (int k = 0; k < K; k += 4) {
        float4 a[RPW];
#pragma unroll
        for (int r = 0; r < RPW; ++r)
            a[r] = *(const float4*)(act + (r0 + r) * AST + k);   // broadcast LDS.128
#pragma unroll
        for (int kk = 0; kk < 4; ++kk) {
            const float* wr = wbase + (size_t)(k + kk) * ldw;
            ulonglong2 w0 = *(const ulonglong2*)(wr);            // cols c..c+3 (coalesced)
            ulonglong2 w1 = *(const ulonglong2*)(wr + 128);      // cols 128+c..+3
#pragma unroll
            for (int r = 0; r < RPW; ++r) {
                u64 av = bcast2(fcomp(a[r], kk));
                fma2(acc[r][0], av, w0.x);
                fma2(acc[r][1], av, w0.y);
                fma2(acc[r][2], av, w1.x);
                fma2(acc[r][3], av, w1.y);
            }
        }
    }
}

__device__ __forceinline__ void zero_acc(u64 acc[RPW][4]) {
#pragma unroll
    for (int r = 0; r < RPW; ++r)
#pragma unroll
        for (int j = 0; j < 4; ++j) acc[r][j] = 0ULL;
}

__device__ __forceinline__ void epilogue(u64 acc[RPW][4], float* out,
        const float* __restrict__ bias, bool relu, int r0, int lane)
{
    float4 b0 = *(const float4*)(bias + lane * 4);
    float4 b1 = *(const float4*)(bias + 128 + lane * 4);
#pragma unroll
    for (int r = 0; r < RPW; ++r) {
        float2 p0 = unpk(acc[r][0]);
        float2 p1 = unpk(acc[r][1]);
        float2 p2 = unpk(acc[r][2]);
        float2 p3 = unpk(acc[r][3]);
        float4 o0 = make_float4(p0.x + b0.x, p0.y + b0.y, p1.x + b0.z, p1.y + b0.w);
        float4 o1 = make_float4(p2.x + b1.x, p2.y + b1.y, p3.x + b1.z, p3.y + b1.w);
        if (relu) {
            o0.x = fmaxf(o0.x, 0.f); o0.y = fmaxf(o0.y, 0.f);
            o0.z = fmaxf(o0.z, 0.f); o0.w = fmaxf(o0.w, 0.f);
            o1.x = fmaxf(o1.x, 0.f); o1.y = fmaxf(o1.y, 0.f);
            o1.z = fmaxf(o1.z, 0.f); o1.w = fmaxf(o1.w, 0.f);
        }
        *(float4*)(out + (r0 + r) * NC + lane * 4) = o0;
        *(float4*)(out + (r0 + r) * NC + 128 + lane * 4) = o1;
    }
}

__global__ void __launch_bounds__(NTHR, 1)
meshcaster_kernel(
    const int*   __restrict__ verts,  const float* __restrict__ barys,
    const float* __restrict__ views,  const float* __restrict__ emb,
    const float* __restrict__ w_proj, const float* __restrict__ b_proj,
    const float* __restrict__ view_W, const float* __restrict__ view_b,
    const float* __restrict__ vert_W, const float* __restrict__ vert_b,
    const float* __restrict__ aW1,    const float* __restrict__ ab1,
    const float* __restrict__ aW2,    const float* __restrict__ ab2,
    const float* __restrict__ cW1,    const float* __restrict__ cb1,
    const float* __restrict__ cW2,    const float* __restrict__ cb2,
    float* __restrict__ out)
{
    extern __shared__ float smem[];
    float* VE = smem;               // [32][256] vertex embeds (kept for color concat)
    float* VV = VE + RPC * NC;      // [32][256] view branch result (kept for color concat)
    float* B0 = VV + RPC * NC;      // [32][256] work
    float* B1 = B0 + RPC * NC;      // [32][256] work
    float* EM = B1 + RPC * NC;      // [32][36]  sincos embedding

    const int tid = threadIdx.x, warp = tid >> 5, lane = tid & 31;
    const int r0 = warp * RPW;
    const int base = blockIdx.x * RPC;

    // ---- Phase 1: gather + max_norm(1.0) renorm + barycentric blend -> VE ----
    for (int rr = 0; rr < RPW; ++rr) {
        int r = r0 + rr, row = base + r, mesh = row & 7;
        float4 acc0 = make_float4(0.f, 0.f, 0.f, 0.f);
        float4 acc1 = make_float4(0.f, 0.f, 0.f, 0.f);
#pragma unroll
        for (int v = 0; v < 3; ++v) {
            int idx = verts[row * 3 + v] + 1;
            const float* ep = emb + ((size_t)mesh * NTAB + (size_t)idx) * NC;
            float4 e0 = *(const float4*)(ep + lane * 4);
            float4 e1 = *(const float4*)(ep + 128 + lane * 4);
            float ss = e0.x*e0.x + e0.y*e0.y + e0.z*e0.z + e0.w*e0.w
                     + e1.x*e1.x + e1.y*e1.y + e1.z*e1.z + e1.w*e1.w;
#pragma unroll
            for (int o = 16; o > 0; o >>= 1) ss += __shfl_xor_sync(0xffffffffu, ss, o);
            float nrm = sqrtf(ss);
            float sc = barys[row * 3 + v];
            if (nrm > 1.f) sc *= 1.f / fmaxf(nrm, 1e-7f);
            acc0.x += sc * e0.x; acc0.y += sc * e0.y; acc0.z += sc * e0.z; acc0.w += sc * e0.w;
            acc1.x += sc * e1.x; acc1.y += sc * e1.y; acc1.z += sc * e1.z; acc1.w += sc * e1.w;
        }
        *(float4*)(VE + r * NC + lane * 4) = acc0;
        *(float4*)(VE + r * NC + 128 + lane * 4) = acc1;
    }

    // ---- Phase 2: sincos embedding (order: [l][sin|cos][xyz]) -> EM ----
    for (int t = lane; t < RPW * VD; t += 32) {
        int rr = t / VD, j = t % VD;
        int l = j / 6, rem = j % 6, s = rem / 3, d = rem % 3;
        float x = views[(base + r0 + rr) * 3 + d];
        float fx = (float)(1 << l) * x;
        EM[(r0 + rr) * VD + j] = s ? cosf(fx) : sinf(fx);
    }
    __syncwarp();

    u64 acc[RPW][4];

    // ---- view branch: proj (no act), then 2x Linear+ReLU ----
    zero_acc(acc);
    acc_block<VD, VD>(acc, EM, w_proj, NC, 0, r0, lane);
    epilogue(acc, B0, b_proj, false, r0, lane);
    __syncwarp();
    zero_acc(acc);
    acc_block<NC, NC>(acc, B0, view_W, NC, 0, r0, lane);
    epilogue(acc, B1, view_b, true, r0, lane);
    __syncwarp();
    zero_acc(acc);
    acc_block<NC, NC>(acc, B1, view_W + NC * NC, NC, 0, r0, lane);
    epilogue(acc, VV, view_b + NC, true, r0, lane);
    __syncwarp();

    // ---- alpha branch: 2x Linear+ReLU on VE, then Linear (no act) ----
    zero_acc(acc);
    acc_block<NC, NC>(acc, VE, vert_W, NC, 0, r0, lane);
    epilogue(acc, B0, vert_b, true, r0, lane);
    __syncwarp();
    zero_acc(acc);
    acc_block<NC, NC>(acc, B0, vert_W + NC * NC, NC, 0, r0, lane);
    epilogue(acc, B1, vert_b + NC, true, r0, lane);
    __syncwarp();
    zero_acc(acc);
    acc_block<NC, NC>(acc, B1, aW1, NC, 0, r0, lane);
    epilogue(acc, B0, ab1, false, r0, lane);
    __syncwarp();

    // ---- alpha head: t @ alpha_W2 + b2 (scalar per row) ----
    float ab2v = ab2[0];
    float alphas[RPW];
    for (int rr = 0; rr < RPW; ++rr) {
        const float* t = B0 + (r0 + rr) * NC;
        float s = 0.f;
#pragma unroll
        for (int g = 0; g < 2; ++g) {
            int off = g * 128 + lane * 4;
#pragma unroll
            for (int j = 0; j < 4; ++j) s += t[off + j] * aW2[off + j];
        }
#pragma unroll
        for (int o = 16; o > 0; o >>= 1) s += __shfl_xor_sync(0xffffffffu, s, o);
        alphas[rr] = s + ab2v;
    }
    __syncwarp();

    // ---- color layer 1: [VV | VE] (512) @ cW1 (512x512) + cb1, no act ----
    // output cols 0..255 -> B0
    zero_acc(acc);
    acc_block<NC, NC>(acc, VV, cW1, 512, 0, r0, lane);
    acc_block<NC, NC>(acc, VE, cW1 + 256 * 512, 512, 0, r0, lane);
    epilogue(acc, B0, cb1, false, r0, lane);
    // output cols 256..511 -> B1
    zero_acc(acc);
    acc_block<NC, NC>(acc, VV, cW1, 512, 256, r0, lane);
    acc_block<NC, NC>(acc, VE, cW1 + 256 * 512, 512, 256, r0, lane);
    epilogue(acc, B1, cb1 + 256, false, r0, lane);
    __syncwarp();

    // ---- color head: u (512) @ cW2 (512x3) + cb2, write [rgb, alpha] ----
    for (int rr = 0; rr < RPW; ++rr) {
        int row = base + r0 + rr;
        const float* u0 = B0 + (r0 + rr) * NC;   // k 0..255
        const float* u1 = B1 + (r0 + rr) * NC;   // k 256..511
        float s0 = 0.f, s1 = 0.f, s2 = 0.f;
#pragma unroll
        for (int g = 0; g < 2; ++g) {
            int off = g * 128 + lane * 4;
#pragma unroll
            for (int j = 0; j < 4; ++j) {
                float uv = u0[off + j];
                const float* w = cW2 + (size_t)(off + j) * 3;
                s0 += uv * w[0]; s1 += uv * w[1]; s2 += uv * w[2];
                uv = u1[off + j];
                w = cW2 + (size_t)(256 + off + j) * 3;
                s0 += uv * w[0]; s1 += uv * w[1]; s2 += uv * w[2];
            }
        }
#pragma unroll
        for (int o = 16; o > 0; o >>= 1) {
            s0 += __shfl_xor_sync(0xffffffffu, s0, o);
            s1 += __shfl_xor_sync(0xffffffffu, s1, o);
            s2 += __shfl_xor_sync(0xffffffffu, s2, o);
        }
        if (lane == 0) {
            float4 ov = make_float4(s0 + cb2[0], s1 + cb2[1], s2 + cb2[2], alphas[rr]);
            *(float4*)(out + (size_t)row * 4) = ov;
        }
    }
}

extern "C" void kernel_launch(void* const* d_in, const int* in_sizes, int n_in,
                              void* d_out, int out_size)
{
    const int*   verts  = (const int*)  d_in[0];
    const float* barys  = (const float*)d_in[1];
    const float* views  = (const float*)d_in[2];
    const float* emb    = (const float*)d_in[3];
    const float* w_proj = (const float*)d_in[4];
    const float* b_proj = (const float*)d_in[5];
    const float* view_W = (const float*)d_in[6];
    const float* view_b = (const float*)d_in[7];
    const float* vert_W = (const float*)d_in[8];
    const float* vert_b = (const float*)d_in[9];
    const float* aW1    = (const float*)d_in[10];
    const float* ab1    = (const float*)d_in[11];
    const float* aW2    = (const float*)d_in[12];
    const float* ab2    = (const float*)d_in[13];
    const float* cW1    = (const float*)d_in[14];
    const float* cb1    = (const float*)d_in[15];
    const float* cW2    = (const float*)d_in[16];
    const float* cb2    = (const float*)d_in[17];
    float* out = (float*)d_out;

    size_t smem = (size_t)(4 * RPC * NC + RPC * VD) * sizeof(float);  // 135,680 B
    cudaFuncSetAttribute(meshcaster_kernel,
                         cudaFuncAttributeMaxDynamicSharedMemorySize, (int)smem);
    meshcaster_kernel<<<NROWS / RPC, NTHR, smem>>>(
        verts, barys, views, emb, w_proj, b_proj, view_W, view_b,
        vert_W, vert_b, aW1, ab1, aW2, ab2, cW1, cb1, cW2, cb2, out);
}

// round 2
// speedup vs baseline: 1.0006x; 1.0006x over previous
#include <cuda_runtime.h>
#include <math.h>

#define NROWS   262144      // 32768 samples * 8 meshes
#define NC      256
#define NTAB    50001
#define VD      36
#define RPC     32          // rows per CTA
#define RPW     4           // rows per warp
#define NTHR    256

typedef unsigned long long u64;

// ---- packed f32x2 helpers (Blackwell FFMA2 path) ----
__device__ __forceinline__ u64 bcast2(float x) {
    u64 r; asm("mov.b64 %0, {%1, %1};" : "=l"(r) : "f"(x)); return r;
}
__device__ __forceinline__ void fma2(u64 &d, u64 a, u64 b) {
    asm("fma.rn.f32x2 %0, %1, %2, %0;" : "+l"(d) : "l"(a), "l"(b));
}
__device__ __forceinline__ float2 unpk(u64 v) {
    float x, y; asm("mov.b64 {%0, %1}, %2;" : "=f"(x), "=f"(y) : "l"(v));
    return make_float2(x, y);
}
__device__ __forceinline__ float fcomp(const float4 &v, int i) {
    return (i == 0) ? v.x : (i == 1) ? v.y : (i == 2) ? v.z : v.w;
}

// Accumulate a K-chunk of a dense layer into packed accumulators.
// Warp layout: 4 rows (r0..r0+3), lane owns cols {lane*4..+3} and {128+lane*4..+3}
// acc[r][0..1] -> cols lane*4 + {0,1},{2,3}; acc[r][2..3] -> cols 128+lane*4 + {0,1},{2,3}
template<int K, int AST>
__device__ __forceinline__ void acc_block(u64 acc[RPW][4],
        const float *act, const float* __restrict__ W,
        int ldw, int colBase, int r0, int lane)
{
    const float* wbase = W + colBase + lane * 4;
#pragma unroll 2
    for (int k = 0; k < K; k += 4) {
        float4 a[RPW];
#pragma unroll
        for (int r = 0; r < RPW; ++r)
            a[r] = *(const float4*)(act + (r0 + r) * AST + k);   // broadcast LDS.128
#pragma unroll
        for (int kk = 0; kk < 4; ++kk) {
            const float* wr = wbase + (size_t)(k + kk) * ldw;
            ulonglong2 w0 = *(const ulonglong2*)(wr);            // cols c..c+3 (coalesced)
            ulonglong2 w1 = *(const ulonglong2*)(wr + 128);      // cols 128+c..+3
#pragma unroll
            for (int r = 0; r < RPW; ++r) {
                u64 av = bcast2(fcomp(a[r], kk));
                fma2(acc[r][0], av, w0.x);
                fma2(acc[r][1], av, w0.y);
                fma2(acc[r][2], av, w1.x);
                fma2(acc[r][3], av, w1.y);
            }
        }
    }
}

__device__ __forceinline__ void zero_acc(u64 acc[RPW][4]) {
#pragma unroll
    for (int r = 0; r < RPW; ++r)
#pragma unroll
        for (int j = 0; j < 4; ++j) acc[r][j] = 0ULL;
}

__device__ __forceinline__ void epilogue(u64 acc[RPW][4], float* out,
        const float* __restrict__ bias, bool relu, int r0, int lane)
{
    float4 b0 = *(const float4*)(bias + lane * 4);
    float4 b1 = *(const float4*)(bias + 128 + lane * 4);
#pragma unroll
    for (int r = 0; r < RPW; ++r) {
        float2 p0 = unpk(acc[r][0]);
        float2 p1 = unpk(acc[r][1]);
        float2 p2 = unpk(acc[r][2]);
        float2 p3 = unpk(acc[r][3]);
        float4 o0 = make_float4(p0.x + b0.x, p0.y + b0.y, p1.x + b0.z, p1.y + b0.w);
        float4 o1 = make_float4(p2.x + b1.x, p2.y + b1.y, p3.x + b1.z, p3.y + b1.w);
        if (relu) {
            o0.x = fmaxf(o0.x, 0.f); o0.y = fmaxf(o0.y, 0.f);
            o0.z = fmaxf(o0.z, 0.f); o0.w = fmaxf(o0.w, 0.f);
            o1.x = fmaxf(o1.x, 0.f); o1.y = fmaxf(o1.y, 0.f);
            o1.z = fmaxf(o1.z, 0.f); o1.w = fmaxf(o1.w, 0.f);
        }
        *(float4*)(out + (r0 + r) * NC + lane * 4) = o0;
        *(float4*)(out + (r0 + r) * NC + 128 + lane * 4) = o1;
    }
}

__global__ void __launch_bounds__(NTHR, 1)
meshcaster_kernel(
    const int*   __restrict__ verts,  const float* __restrict__ barys,
    const float* __restrict__ views,  const float* __restrict__ emb,
    const float* __restrict__ w_proj, const float* __restrict__ b_proj,
    const float* __restrict__ view_W, const float* __restrict__ view_b,
    const float* __restrict__ vert_W, const float* __restrict__ vert_b,
    const float* __restrict__ aW1,    const float* __restrict__ ab1,
    const float* __restrict__ aW2,    const float* __restrict__ ab2,
    const float* __restrict__ cW1,    const float* __restrict__ cb1,
    const float* __restrict__ cW2,    const float* __restrict__ cb2,
    float* __restrict__ out)
{
    extern __shared__ float smem[];
    float* VE = smem;               // [32][256] vertex embeds (kept for color concat)
    float* VV = VE + RPC * NC;      // [32][256] view branch result (kept for color concat)
    float* B0 = VV + RPC * NC;      // [32][256] work
    float* B1 = B0 + RPC * NC;      // [32][256] work
    float* EM = B1 + RPC * NC;      // [32][36]  sincos embedding

    const int tid = threadIdx.x, warp = tid >> 5, lane = tid & 31;
    const int r0 = warp * RPW;
    const int base = blockIdx.x * RPC;

    // ---- Phase 1: gather + max_norm(1.0) renorm + barycentric blend -> VE ----
    for (int rr = 0; rr < RPW; ++rr) {
        int r = r0 + rr, row = base + r, mesh = row & 7;
        float4 acc0 = make_float4(0.f, 0.f, 0.f, 0.f);
        float4 acc1 = make_float4(0.f, 0.f, 0.f, 0.f);
#pragma unroll
        for (int v = 0; v < 3; ++v) {
            int idx = verts[row * 3 + v] + 1;
            const float* ep = emb + ((size_t)mesh * NTAB + (size_t)idx) * NC;
            float4 e0 = *(const float4*)(ep + lane * 4);
            float4 e1 = *(const float4*)(ep + 128 + lane * 4);
            float ss = e0.x*e0.x + e0.y*e0.y + e0.z*e0.z + e0.w*e0.w
                     + e1.x*e1.x + e1.y*e1.y + e1.z*e1.z + e1.w*e1.w;
#pragma unroll
            for (int o = 16; o > 0; o >>= 1) ss += __shfl_xor_sync(0xffffffffu, ss, o);
            float nrm = sqrtf(ss);
            float sc = barys[row * 3 + v];
            if (nrm > 1.f) sc *= 1.f / fmaxf(nrm, 1e-7f);
            acc0.x += sc * e0.x; acc0.y += sc * e0.y; acc0.z += sc * e0.z; acc0.w += sc * e0.w;
            acc1.x += sc * e1.x; acc1.y += sc * e1.y; acc1.z += sc * e1.z; acc1.w += sc * e1.w;
        }
        *(float4*)(VE + r * NC + lane * 4) = acc0;
        *(float4*)(VE + r * NC + 128 + lane * 4) = acc1;
    }

    // ---- Phase 2: sincos embedding (order: [l][sin|cos][xyz]) -> EM ----
    for (int t = lane; t < RPW * VD; t += 32) {
        int rr = t / VD, j = t % VD;
        int l = j / 6, rem = j % 6, s = rem / 3, d = rem % 3;
        float x = views[(base + r0 + rr) * 3 + d];
        float fx = (float)(1 << l) * x;
        EM[(r0 + rr) * VD + j] = s ? cosf(fx) : sinf(fx);
    }
    __syncwarp();

    u64 acc[RPW][4];

    // ---- view branch: proj (no act), then 2x Linear+ReLU ----
    zero_acc(acc);
    acc_block<VD, VD>(acc, EM, w_proj, NC, 0, r0, lane);
    epilogue(acc, B0, b_proj, false, r0, lane);
    __syncwarp();
    zero_acc(acc);
    acc_block<NC, NC>(acc, B0, view_W, NC, 0, r0, lane);
    epilogue(acc, B1, view_b, true, r0, lane);
    __syncwarp();
    zero_acc(acc);
    acc_block<NC, NC>(acc, B1, view_W + NC * NC, NC, 0, r0, lane);
    epilogue(acc, VV, view_b + NC, true, r0, lane);
    __syncwarp();

    // ---- alpha branch: 2x Linear+ReLU on VE, then Linear (no act) ----
    zero_acc(acc);
    acc_block<NC, NC>(acc, VE, vert_W, NC, 0, r0, lane);
    epilogue(acc, B0, vert_b, true, r0, lane);
    __syncwarp();
    zero_acc(acc);
    acc_block<NC, NC>(acc, B0, vert_W + NC * NC, NC, 0, r0, lane);
    epilogue(acc, B1, vert_b + NC, true, r0, lane);
    __syncwarp();
    zero_acc(acc);
    acc_block<NC, NC>(acc, B1, aW1, NC, 0, r0, lane);
    epilogue(acc, B0, ab1, false, r0, lane);
    __syncwarp();

    // ---- alpha head: t @ alpha_W2 + b2 (scalar per row) ----
    float ab2v = ab2[0];
    float alphas[RPW];
    for (int rr = 0; rr < RPW; ++rr) {
        const float* t = B0 + (r0 + rr) * NC;
        float s = 0.f;
#pragma unroll
        for (int g = 0; g < 2; ++g) {
            int off = g * 128 + lane * 4;
#pragma unroll
            for (int j = 0; j < 4; ++j) s += t[off + j] * aW2[off + j];
        }
#pragma unroll
        for (int o = 16; o > 0; o >>= 1) s += __shfl_xor_sync(0xffffffffu, s, o);
        alphas[rr] = s + ab2v;
    }
    __syncwarp();

    // ---- color layer 1: [VV | VE] (512) @ cW1 (512x512) + cb1, no act ----
    // output cols 0..255 -> B0
    zero_acc(acc);
    acc_block<NC, NC>(acc, VV, cW1, 512, 0, r0, lane);
    acc_block<NC, NC>(acc, VE, cW1 + 256 * 512, 512, 0, r0, lane);
    epilogue(acc, B0, cb1, false, r0, lane);
    // output cols 256..511 -> B1
    zero_acc(acc);
    acc_block<NC, NC>(acc, VV, cW1, 512, 256, r0, lane);
    acc_block<NC, NC>(acc, VE, cW1 + 256 * 512, 512, 256, r0, lane);
    epilogue(acc, B1, cb1 + 256, false, r0, lane);
    __syncwarp();

    // ---- color head: u (512) @ cW2 (512x3) + cb2, write [rgb, alpha] ----
    for (int rr = 0; rr < RPW; ++rr) {
        int row = base + r0 + rr;
        const float* u0 = B0 + (r0 + rr) * NC;   // k 0..255
        const float* u1 = B1 + (r0 + rr) * NC;   // k 256..511
        float s0 = 0.f, s1 = 0.f, s2 = 0.f;
#pragma unroll
        for (int g = 0; g < 2; ++g) {
            int off = g * 128 + lane * 4;
#pragma unroll
            for (int j = 0; j < 4; ++j) {
                float uv = u0[off + j];
                const float* w = cW2 + (size_t)(off + j) * 3;
                s0 += uv * w[0]; s1 += uv * w[1]; s2 += uv * w[2];
                uv = u1[off + j];
                w = cW2 + (size_t)(256 + off + j) * 3;
                s0 += uv * w[0]; s1 += uv * w[1]; s2 += uv * w[2];
            }
        }
#pragma unroll
        for (int o = 16; o > 0; o >>= 1) {
            s0 += __shfl_xor_sync(0xffffffffu, s0, o);
            s1 += __shfl_xor_sync(0xffffffffu, s1, o);
            s2 += __shfl_xor_sync(0xffffffffu, s2, o);
        }
        if (lane == 0) {
            float4 ov = make_float4(s0 + cb2[0], s1 + cb2[1], s2 + cb2[2], alphas[rr]);
            *(float4*)(out + (size_t)row * 4) = ov;
        }
    }
}

extern "C" void kernel_launch(void* const* d_in, const int* in_sizes, int n_in,
                              void* d_out, int out_size)
{
    const int*   verts  = (const int*)  d_in[0];
    const float* barys  = (const float*)d_in[1];
    const float* views  = (const float*)d_in[2];
    const float* emb    = (const float*)d_in[3];
    const float* w_proj = (const float*)d_in[4];
    const float* b_proj = (const float*)d_in[5];
    const float* view_W = (const float*)d_in[6];
    const float* view_b = (const float*)d_in[7];
    const float* vert_W = (const float*)d_in[8];
    const float* vert_b = (const float*)d_in[9];
    const float* aW1    = (const float*)d_in[10];
    const float* ab1    = (const float*)d_in[11];
    const float* aW2    = (const float*)d_in[12];
    const float* ab2    = (const float*)d_in[13];
    const float* cW1    = (const float*)d_in[14];
    const float* cb1    = (const float*)d_in[15];
    const float* cW2    = (const float*)d_in[16];
    const float* cb2    = (const float*)d_in[17];
    float* out = (float*)d_out;

    size_t smem = (size_t)(4 * RPC * NC + RPC * VD) * sizeof(float);  // 135,680 B
    cudaFuncSetAttribute(meshcaster_kernel,
                         cudaFuncAttributeMaxDynamicSharedMemorySize, (int)smem);
    meshcaster_kernel<<<NROWS / RPC, NTHR, smem>>>(
        verts, barys, views, emb, w_proj, b_proj, view_W, view_b,
        vert_W, vert_b, aW1, ab1, aW2, ab2, cW1, cb1, cW2, cb2, out);
}